// round 10
// baseline (speedup 1.0000x reference)
#include <cuda_runtime.h>
#include <cuda_fp16.h>
#include <cstdint>
#include <cfloat>

#define NPTS 1536
#define TLEN 20
#define HDIM 64
#define EDIM 16
#define MDIM 128
#define IPB  8              // i's per block (one per warp)
#define JC   32             // j rows per chunk
#define NCHUNK 48
#define JSPLIT 3            // j-range splits
#define CPB (NCHUNK / JSPLIT)   // 16 chunks -> 8 pairs
#define NPAIR (CPB / 2)
#define THREADS 256
#define APITCH 144          // halves per smem row (72 words == 8 mod 32: LDS.64 conflict-free)
#define ABUF_BYTES (JC * APITCH * 2)            // 9216
#define OFF_W2 (6 * ABUF_BYTES)                 // 55296
#define SMEM_SZ (OFF_W2 + HDIM * APITCH * 2)    // 73728

// scratch (__device__ globals: allocation-free rule). Stored k-PERMUTED (mperm).
__device__ __half g_Ah[NPTS * MDIM];
__device__ __half g_Bh[NPTS * MDIM];
__device__ __half g_W2h[HDIM * MDIM];   // W2^T, h-major, permuted fp16

// Permutation within each 16-k group so mma fragment halves are contiguous:
__host__ __device__ __forceinline__ int mperm(int m) {
    int g = m >> 4, w = m & 15;
    int pos = (w < 8) ? ((w >> 1) * 4 + (w & 1))
                      : (((w - 8) >> 1) * 4 + 2 + (w & 1));
    return g * 16 + pos;
}

// ---------------------------------------------------------------------------
// Precompute: A[j,m], B[j,m] (fp16, permuted) + W2^T fp16 permuted + zero out
// ---------------------------------------------------------------------------
__global__ void prep_kernel(const float* __restrict__ hidden,
                            const float* __restrict__ gt,
                            const float* __restrict__ We,
                            const float* __restrict__ be,
                            const float* __restrict__ W1,
                            const float* __restrict__ b1,
                            const float* __restrict__ W2,
                            float* __restrict__ out) {
    int j = blockIdx.x;
    int m = threadIdx.x;               // 0..127
    __shared__ float hs[HDIM];
    __shared__ float ev[2];
    if (m < HDIM) hs[m] = hidden[j * HDIM + m];
    if (m < 2)    ev[m] = gt[(j * TLEN + (TLEN - 1)) * 2 + m];
    __syncthreads();

    float p0 = 0.f, p1 = 0.f, q = 0.f;
#pragma unroll
    for (int e = 0; e < EDIM; e++) {
        float wv = W1[(HDIM + e) * MDIM + m];
        p0 += We[e] * wv;
        p1 += We[EDIM + e] * wv;
        q  += be[e] * wv;
    }
    float s = 0.f;
#pragma unroll 8
    for (int h = 0; h < HDIM; h++) s += hs[h] * W1[h * MDIM + m];

    float d = ev[0] * p0 + ev[1] * p1;
    int mp = mperm(m);
    g_Bh[j * MDIM + mp] = __float2half(d);
    g_Ah[j * MDIM + mp] = __float2half(s + d + q + b1[m]);

    if (m < HDIM) out[j * HDIM + m] = 0.f;                 // zero output (atomicMax base)
    if (j < HDIM) g_W2h[j * MDIM + mp] = __float2half(W2[m * HDIM + j]);
}

// ---------------------------------------------------------------------------
// Main: grid = (NPTS/IPB)*JSPLIT = 576 blocks, 256 threads (8 warps, warp=i).
// R4 inner loop; 6-buffer cp.async pipeline, ONE __syncthreads per 2 chunks.
// ---------------------------------------------------------------------------
__global__ void __launch_bounds__(THREADS, 2)
main_kernel(const float* __restrict__ b2, float* __restrict__ out) {
    extern __shared__ __align__(16) char smem[];
    __half* w2t = (__half*)(smem + OFF_W2);

    const int tid  = threadIdx.x;
    const int w    = tid >> 5;
    const int lane = tid & 31;
    const int ig   = blockIdx.x / JSPLIT;
    const int js   = blockIdx.x % JSPLIT;
    const int i    = ig * IPB + w;
    const int jc0  = js * CPB;

    const int fr = lane >> 2;          // fragment row (0..7)
    const int fc = lane & 3;           // fragment k-quad (0..3)

    // ---- stage A chunk jc into buffer buf (512 x 16B segs, 2 iters) ----
    auto stageA = [&](int buf, int jc) {
        const __half* src = g_Ah + jc * JC * MDIM;
        char* base = smem + buf * ABUF_BYTES;
#pragma unroll
        for (int k = 0; k < 2; k++) {
            int idx = tid + k * THREADS;                   // 0..511
            int row = idx >> 4, seg = idx & 15;
            uint32_t dst = (uint32_t)__cvta_generic_to_shared(
                base + (row * APITCH + seg * 8) * 2);
            asm volatile("cp.async.ca.shared.global [%0], [%1], 16;"
                         :: "r"(dst), "l"(src + idx * 8) : "memory");
        }
    };

    // ---- prologue: W2 (1024 segs, 4 iters) + chunks 0,1 -> group G0; 2,3 -> G1
#pragma unroll
    for (int k = 0; k < 4; k++) {
        int idx = tid + k * THREADS;                       // 0..1023
        int h = idx >> 4, s = idx & 15;
        uint32_t dst = (uint32_t)__cvta_generic_to_shared(&w2t[h * APITCH + s * 8]);
        asm volatile("cp.async.ca.shared.global [%0], [%1], 16;"
                     :: "r"(dst), "l"(g_W2h + h * MDIM + s * 8) : "memory");
    }
    stageA(0, jc0 + 0); stageA(1, jc0 + 1);
    asm volatile("cp.async.commit_group;" ::: "memory");
    stageA(2, jc0 + 2); stageA(3, jc0 + 3);
    asm volatile("cp.async.commit_group;" ::: "memory");

    // ---- B[i] fragments ----
    __half2 bf[8][2];
#pragma unroll
    for (int ks = 0; ks < 8; ks++) {
        uint2 bv = *(const uint2*)&g_Bh[i * MDIM + ks * 16 + fc * 4];
        bf[ks][0] = *(__half2*)&bv.x;
        bf[ks][1] = *(__half2*)&bv.y;
    }

    float mx[8][2];
#pragma unroll
    for (int t = 0; t < 8; t++) { mx[t][0] = -FLT_MAX; mx[t][1] = -FLT_MAX; }

    const __half2 zero2 = __float2half2_rn(0.f);

    // ---- compute one chunk from buffer buf (exact R4 body) ----
    auto computeChunk = [&](int buf) {
        const __half* As = (const __half*)(smem + buf * ABUF_BYTES);
        float cacc[2][8][4];
#pragma unroll
        for (int jt = 0; jt < 2; jt++)
#pragma unroll
            for (int ht = 0; ht < 8; ht++)
#pragma unroll
                for (int r = 0; r < 4; r++) cacc[jt][ht][r] = 0.f;

#pragma unroll
        for (int ks = 0; ks < 8; ks++) {
            const int koff = ks * 16 + fc * 4;
            uint32_t za[2][4];
#pragma unroll
            for (int jt = 0; jt < 2; jt++) {
                uint2 v0 = *(const uint2*)&As[(jt * 16 + fr) * APITCH + koff];     // a0|a2
                uint2 v1 = *(const uint2*)&As[(jt * 16 + 8 + fr) * APITCH + koff]; // a1|a3
                __half2 a0 = __hmax2(__hsub2(*(__half2*)&v0.x, bf[ks][0]), zero2);
                __half2 a2 = __hmax2(__hsub2(*(__half2*)&v0.y, bf[ks][1]), zero2);
                __half2 a1 = __hmax2(__hsub2(*(__half2*)&v1.x, bf[ks][0]), zero2);
                __half2 a3 = __hmax2(__hsub2(*(__half2*)&v1.y, bf[ks][1]), zero2);
                za[jt][0] = *(uint32_t*)&a0;
                za[jt][1] = *(uint32_t*)&a1;
                za[jt][2] = *(uint32_t*)&a2;
                za[jt][3] = *(uint32_t*)&a3;
            }
#pragma unroll
            for (int ht = 0; ht < 8; ht++) {
                uint2 wb = *(const uint2*)&w2t[(ht * 8 + fr) * APITCH + koff];     // b0|b1
#pragma unroll
                for (int jt = 0; jt < 2; jt++) {
                    asm volatile(
                        "mma.sync.aligned.m16n8k16.row.col.f32.f16.f16.f32 "
                        "{%0,%1,%2,%3},{%4,%5,%6,%7},{%8,%9},{%0,%1,%2,%3};"
                        : "+f"(cacc[jt][ht][0]), "+f"(cacc[jt][ht][1]),
                          "+f"(cacc[jt][ht][2]), "+f"(cacc[jt][ht][3])
                        : "r"(za[jt][0]), "r"(za[jt][1]), "r"(za[jt][2]), "r"(za[jt][3]),
                          "r"(wb.x), "r"(wb.y));
                }
            }
        }
#pragma unroll
        for (int jt = 0; jt < 2; jt++)
#pragma unroll
            for (int ht = 0; ht < 8; ht++) {
                mx[ht][0] = fmaxf(mx[ht][0], fmaxf(cacc[jt][ht][0], cacc[jt][ht][2]));
                mx[ht][1] = fmaxf(mx[ht][1], fmaxf(cacc[jt][ht][1], cacc[jt][ht][3]));
            }
    };

    // ---- mainloop: pairs of chunks, one barrier per pair ----
    int pb = 0;                         // pair buffer index = p % 3
#pragma unroll 1
    for (int p = 0; p < NPAIR; p++) {
        if (p < NPAIR - 1) {
            asm volatile("cp.async.wait_group 1;" ::: "memory");
        } else {
            asm volatile("cp.async.wait_group 0;" ::: "memory");
        }
        __syncthreads();                // data visible CTA-wide; pair p-1 buffers free
        if (p + 2 < NPAIR) {
            int pb2 = pb + 2; if (pb2 >= 3) pb2 -= 3;
            stageA(2 * pb2,     jc0 + 2 * p + 4);
            stageA(2 * pb2 + 1, jc0 + 2 * p + 5);
            asm volatile("cp.async.commit_group;" ::: "memory");
        }
        computeChunk(2 * pb);
        computeChunk(2 * pb + 1);
        if (++pb == 3) pb = 0;
    }

    // ---- reduce max across j-row lanes (same h: lane%4 groups) ----
#pragma unroll
    for (int ht = 0; ht < 8; ht++) {
#pragma unroll
        for (int s = 4; s < 32; s <<= 1) {
            mx[ht][0] = fmaxf(mx[ht][0], __shfl_xor_sync(0xffffffffu, mx[ht][0], s));
            mx[ht][1] = fmaxf(mx[ht][1], __shfl_xor_sync(0xffffffffu, mx[ht][1], s));
        }
    }
    if (lane < 4) {
#pragma unroll
        for (int ht = 0; ht < 8; ht++) {
            int h = ht * 8 + 2 * lane;
            float v0 = fmaxf(mx[ht][0] + b2[h], 0.f);
            float v1 = fmaxf(mx[ht][1] + b2[h + 1], 0.f);
            // relu output >= 0: int-ordered atomicMax exact; out pre-zeroed in prep
            atomicMax((int*)&out[i * HDIM + h],     __float_as_int(v0));
            atomicMax((int*)&out[i * HDIM + h + 1], __float_as_int(v1));
        }
    }
}

// ---------------------------------------------------------------------------
extern "C" void kernel_launch(void* const* d_in, const int* in_sizes, int n_in,
                              void* d_out, int out_size) {
    const float* hidden = (const float*)d_in[0];
    const float* gt     = (const float*)d_in[1];
    const float* We     = (const float*)d_in[2];
    const float* be     = (const float*)d_in[3];
    const float* W1     = (const float*)d_in[4];
    const float* b1     = (const float*)d_in[5];
    const float* W2     = (const float*)d_in[6];
    const float* b2     = (const float*)d_in[7];
    float* out = (float*)d_out;

    prep_kernel<<<NPTS, MDIM>>>(hidden, gt, We, be, W1, b1, W2, out);
    cudaFuncSetAttribute(main_kernel, cudaFuncAttributeMaxDynamicSharedMemorySize, SMEM_SZ);
    main_kernel<<<(NPTS / IPB) * JSPLIT, THREADS, SMEM_SZ>>>(b2, out);
}

// round 13
// speedup vs baseline: 2.2847x; 2.2847x over previous
#include <cuda_runtime.h>
#include <cuda_fp16.h>
#include <cstdint>
#include <cfloat>

#define NPTS 1536
#define TLEN 20
#define HDIM 64
#define EDIM 16
#define MDIM 128
#define IPB  8              // i's per block (one per warp)
#define JC   32             // j rows per chunk
#define NCHUNK 48
#define JSPLIT 3
#define CPB (NCHUNK / JSPLIT)   // 16 chunks
#define NPAIR (CPB / 2)         // 8 pairs
#define THREADS 256
#define APITCH 144          // halves per smem row (72 words == 8 mod 32: LDS.64 conflict-free)
#define ABUF_BYTES (JC * APITCH * 2)            // 9216
#define OFF_W2 (6 * ABUF_BYTES)                 // 55296
#define SMEM_SZ (OFF_W2 + 16384)                // 71680 (w2c = 1024 x uint4)

// scratch (__device__ globals). A/B stored k-PERMUTED (mperm); W2 as paired frags.
__device__ __half g_Ah[NPTS * MDIM];
__device__ __half g_Bh[NPTS * MDIM];
__device__ uint4  g_W2c[8 * 4 * 32];    // [ks][htp][lane] = {b0,b1}(ht even),{b0,b1}(ht odd)

// Permutation within each 16-k group so mma A fragment halves are contiguous:
__host__ __device__ __forceinline__ int mperm(int m) {
    int g = m >> 4, w = m & 15;
    int pos = (w < 8) ? ((w >> 1) * 4 + (w & 1))
                      : (((w - 8) >> 1) * 4 + 2 + (w & 1));
    return g * 16 + pos;
}

// ---------------------------------------------------------------------------
// Precompute: A[j,m], B[j,m] (fp16, permuted); W2 paired-fragment table; out=0
// grid = NPTS, 128 threads
// ---------------------------------------------------------------------------
__global__ void prep_kernel(const float* __restrict__ hidden,
                            const float* __restrict__ gt,
                            const float* __restrict__ We,
                            const float* __restrict__ be,
                            const float* __restrict__ W1,
                            const float* __restrict__ b1,
                            const float* __restrict__ W2,
                            float* __restrict__ out) {
    int j = blockIdx.x;
    int m = threadIdx.x;               // 0..127
    __shared__ float hs[HDIM];
    __shared__ float ev[2];
    if (m < HDIM) hs[m] = hidden[j * HDIM + m];
    if (m < 2)    ev[m] = gt[(j * TLEN + (TLEN - 1)) * 2 + m];
    __syncthreads();

    float p0 = 0.f, p1 = 0.f, q = 0.f;
#pragma unroll
    for (int e = 0; e < EDIM; e++) {
        float wv = W1[(HDIM + e) * MDIM + m];
        p0 += We[e] * wv;
        p1 += We[EDIM + e] * wv;
        q  += be[e] * wv;
    }
    float s = 0.f;
#pragma unroll 8
    for (int h = 0; h < HDIM; h++) s += hs[h] * W1[h * MDIM + m];

    float d = ev[0] * p0 + ev[1] * p1;
    int mp = mperm(m);
    g_Bh[j * MDIM + mp] = __float2half(d);
    g_Ah[j * MDIM + mp] = __float2half(s + d + q + b1[m]);

    if (m < HDIM) out[j * HDIM + m] = 0.f;     // zero output (atomicMax base)

    // blocks 64..71 additionally build the paired W2 fragment table (ks = j-64)
    if (j >= 64 && j < 72) {
        int ks  = j - 64;
        int htp = m >> 5;              // 0..3
        int ln  = m & 31;
        int fr  = ln >> 2, fc = ln & 3;
        int k0  = ks * 16 + 2 * fc;    // W2 is (M,H)=(128,64) row-major
        int n0  = (2 * htp) * 8 + fr;
        int n1  = n0 + 8;
        __half2 x = __floats2half2_rn(W2[k0 * HDIM + n0],       W2[(k0 + 1) * HDIM + n0]);
        __half2 y = __floats2half2_rn(W2[(k0 + 8) * HDIM + n0], W2[(k0 + 9) * HDIM + n0]);
        __half2 z = __floats2half2_rn(W2[k0 * HDIM + n1],       W2[(k0 + 1) * HDIM + n1]);
        __half2 w4 = __floats2half2_rn(W2[(k0 + 8) * HDIM + n1], W2[(k0 + 9) * HDIM + n1]);
        uint4 v;
        v.x = *(uint32_t*)&x; v.y = *(uint32_t*)&y;
        v.z = *(uint32_t*)&z; v.w = *(uint32_t*)&w4;
        g_W2c[(ks * 4 + htp) * 32 + ln] = v;
    }
}

// ---------------------------------------------------------------------------
// Main: grid = 576 blocks, 256 threads (8 warps, warp = i). R4 body with
// paired-W2 LDS.128; 6-buffer cp.async ring; ONE __syncthreads per 2 chunks.
// ---------------------------------------------------------------------------
__global__ void __launch_bounds__(THREADS, 2)
main_kernel(const float* __restrict__ b2, float* __restrict__ out) {
    extern __shared__ __align__(16) char smem[];
    uint4* w2c = (uint4*)(smem + OFF_W2);       // [1024]

    const int tid  = threadIdx.x;
    const int w    = tid >> 5;
    const int lane = tid & 31;
    const int ig   = blockIdx.x / JSPLIT;
    const int js   = blockIdx.x % JSPLIT;
    const int i    = ig * IPB + w;
    const int jc0  = js * CPB;

    const int fr = lane >> 2;          // fragment row (0..7)
    const int fc = lane & 3;           // fragment k-quad (0..3)

    // ---- stage A chunk jc into buffer buf (512 x 16B segs, 2 iters) ----
    auto stageA = [&](int buf, int jc) {
        const __half* src = g_Ah + jc * JC * MDIM;
        char* base = smem + buf * ABUF_BYTES;
#pragma unroll
        for (int k = 0; k < 2; k++) {
            int idx = tid + k * THREADS;                   // 0..511
            int row = idx >> 4, seg = idx & 15;
            uint32_t dst = (uint32_t)__cvta_generic_to_shared(
                base + (row * APITCH + seg * 8) * 2);
            asm volatile("cp.async.ca.shared.global [%0], [%1], 16;"
                         :: "r"(dst), "l"(src + idx * 8) : "memory");
        }
    };

    // ---- prologue: w2c (1024 uint4, 4 iters) + pair0 -> G0; pair1 -> G1 ----
#pragma unroll
    for (int k = 0; k < 4; k++) {
        int idx = tid + k * THREADS;                       // 0..1023
        uint32_t dst = (uint32_t)__cvta_generic_to_shared(&w2c[idx]);
        asm volatile("cp.async.ca.shared.global [%0], [%1], 16;"
                     :: "r"(dst), "l"(&g_W2c[idx]) : "memory");
    }
    stageA(0, jc0 + 0); stageA(1, jc0 + 1);
    asm volatile("cp.async.commit_group;" ::: "memory");
    stageA(2, jc0 + 2); stageA(3, jc0 + 3);
    asm volatile("cp.async.commit_group;" ::: "memory");

    // ---- B[i] fragments ----
    __half2 bf[8][2];
#pragma unroll
    for (int ks = 0; ks < 8; ks++) {
        uint2 bv = *(const uint2*)&g_Bh[i * MDIM + ks * 16 + fc * 4];
        bf[ks][0] = *(__half2*)&bv.x;
        bf[ks][1] = *(__half2*)&bv.y;
    }

    float mx[8][2];
#pragma unroll
    for (int t = 0; t < 8; t++) { mx[t][0] = -FLT_MAX; mx[t][1] = -FLT_MAX; }

    const __half2 zero2 = __float2half2_rn(0.f);

    // ---- mainloop: pairs of chunks, one barrier per pair, 3-pair buffer ring
#pragma unroll 1
    for (int p = 0; p < NPAIR; p++) {
        if (p < NPAIR - 1) {
            asm volatile("cp.async.wait_group 1;" ::: "memory");
        } else {
            asm volatile("cp.async.wait_group 0;" ::: "memory");
        }
        __syncthreads();                // pair p visible; pair p-1 bufs reusable
        int pm3 = p % 3;
        if (p + 2 < NPAIR) {
            int pb2 = pm3 + 2; if (pb2 >= 3) pb2 -= 3;
            stageA(2 * pb2,     jc0 + 2 * p + 4);
            stageA(2 * pb2 + 1, jc0 + 2 * p + 5);
            asm volatile("cp.async.commit_group;" ::: "memory");
        }

        // ---- compute both chunks of the pair (single body instance) ----
#pragma unroll 1
        for (int q = 0; q < 2; q++) {
            const __half* As = (const __half*)(smem + (2 * pm3 + q) * ABUF_BYTES);
            float acc[2][8][4];
#pragma unroll
            for (int jt = 0; jt < 2; jt++)
#pragma unroll
                for (int ht = 0; ht < 8; ht++)
#pragma unroll
                    for (int r = 0; r < 4; r++) acc[jt][ht][r] = 0.f;

#pragma unroll
            for (int ks = 0; ks < 8; ks++) {
                const int koff = ks * 16 + fc * 4;
                uint32_t za[2][4];
#pragma unroll
                for (int jt = 0; jt < 2; jt++) {
                    uint2 v0 = *(const uint2*)&As[(jt * 16 + fr) * APITCH + koff];     // a0|a2
                    uint2 v1 = *(const uint2*)&As[(jt * 16 + 8 + fr) * APITCH + koff]; // a1|a3
                    __half2 a0 = __hmax2(__hsub2(*(__half2*)&v0.x, bf[ks][0]), zero2);
                    __half2 a2 = __hmax2(__hsub2(*(__half2*)&v0.y, bf[ks][1]), zero2);
                    __half2 a1 = __hmax2(__hsub2(*(__half2*)&v1.x, bf[ks][0]), zero2);
                    __half2 a3 = __hmax2(__hsub2(*(__half2*)&v1.y, bf[ks][1]), zero2);
                    za[jt][0] = *(uint32_t*)&a0;
                    za[jt][1] = *(uint32_t*)&a1;
                    za[jt][2] = *(uint32_t*)&a2;
                    za[jt][3] = *(uint32_t*)&a3;
                }
#pragma unroll
                for (int htp = 0; htp < 4; htp++) {
                    uint4 wv = w2c[(ks * 4 + htp) * 32 + lane];  // one LDS.128, 2 ht tiles
#pragma unroll
                    for (int jt = 0; jt < 2; jt++) {
                        asm volatile(
                            "mma.sync.aligned.m16n8k16.row.col.f32.f16.f16.f32 "
                            "{%0,%1,%2,%3},{%4,%5,%6,%7},{%8,%9},{%0,%1,%2,%3};"
                            : "+f"(acc[jt][2 * htp][0]), "+f"(acc[jt][2 * htp][1]),
                              "+f"(acc[jt][2 * htp][2]), "+f"(acc[jt][2 * htp][3])
                            : "r"(za[jt][0]), "r"(za[jt][1]), "r"(za[jt][2]), "r"(za[jt][3]),
                              "r"(wv.x), "r"(wv.y));
                        asm volatile(
                            "mma.sync.aligned.m16n8k16.row.col.f32.f16.f16.f32 "
                            "{%0,%1,%2,%3},{%4,%5,%6,%7},{%8,%9},{%0,%1,%2,%3};"
                            : "+f"(acc[jt][2 * htp + 1][0]), "+f"(acc[jt][2 * htp + 1][1]),
                              "+f"(acc[jt][2 * htp + 1][2]), "+f"(acc[jt][2 * htp + 1][3])
                            : "r"(za[jt][0]), "r"(za[jt][1]), "r"(za[jt][2]), "r"(za[jt][3]),
                              "r"(wv.z), "r"(wv.w));
                    }
                }
            }
            // fold both j-tiles into running max
#pragma unroll
            for (int jt = 0; jt < 2; jt++)
#pragma unroll
                for (int ht = 0; ht < 8; ht++) {
                    mx[ht][0] = fmaxf(mx[ht][0], fmaxf(acc[jt][ht][0], acc[jt][ht][2]));
                    mx[ht][1] = fmaxf(mx[ht][1], fmaxf(acc[jt][ht][1], acc[jt][ht][3]));
                }
        }
    }

    // ---- reduce max across j-row lanes (same h: lane%4 groups) ----
#pragma unroll
    for (int ht = 0; ht < 8; ht++) {
#pragma unroll
        for (int s = 4; s < 32; s <<= 1) {
            mx[ht][0] = fmaxf(mx[ht][0], __shfl_xor_sync(0xffffffffu, mx[ht][0], s));
            mx[ht][1] = fmaxf(mx[ht][1], __shfl_xor_sync(0xffffffffu, mx[ht][1], s));
        }
    }
    if (lane < 4) {
#pragma unroll
        for (int ht = 0; ht < 8; ht++) {
            int h = ht * 8 + 2 * lane;
            float v0 = fmaxf(mx[ht][0] + b2[h], 0.f);
            float v1 = fmaxf(mx[ht][1] + b2[h + 1], 0.f);
            // relu output >= 0: int-ordered atomicMax exact; out pre-zeroed in prep
            atomicMax((int*)&out[i * HDIM + h],     __float_as_int(v0));
            atomicMax((int*)&out[i * HDIM + h + 1], __float_as_int(v1));
        }
    }
}

// ---------------------------------------------------------------------------
extern "C" void kernel_launch(void* const* d_in, const int* in_sizes, int n_in,
                              void* d_out, int out_size) {
    const float* hidden = (const float*)d_in[0];
    const float* gt     = (const float*)d_in[1];
    const float* We     = (const float*)d_in[2];
    const float* be     = (const float*)d_in[3];
    const float* W1     = (const float*)d_in[4];
    const float* b1     = (const float*)d_in[5];
    const float* W2     = (const float*)d_in[6];
    const float* b2     = (const float*)d_in[7];
    float* out = (float*)d_out;

    prep_kernel<<<NPTS, MDIM>>>(hidden, gt, We, be, W1, b1, W2, out);
    cudaFuncSetAttribute(main_kernel, cudaFuncAttributeMaxDynamicSharedMemorySize, SMEM_SZ);
    main_kernel<<<(NPTS / IPB) * JSPLIT, THREADS, SMEM_SZ>>>(b2, out);
}